// round 15
// baseline (speedup 1.0000x reference)
#include <cuda_runtime.h>

// y[tok][o] = sum_e cos(x[tok][e] + theta[e]) * W[o][e],  E = 16, ntok = 1,048,576
//
// cp.async 4-stage smem ring (128 tokens/stage, rows padded to 20 floats for
// conflict-free MMA-fragment LDS). Per warp: 16-token tiles computed with
// tensor cores: mma.m16n8k8.tf32, 3xTF32 split (zh/zl x wh/wl) for fp32-grade
// accuracy. No shuffles, no scalar matvec. D-fragments stored as float2.

#define BLK 128
#define S   4        // pipeline stages
#define GT  128      // tokens per stage
#define ROWF 20      // floats per padded token row (16 data + 4 pad)

__device__ __forceinline__ unsigned f2tf(float f) {
    unsigned r;
    asm("cvt.rna.tf32.f32 %0, %1;" : "=r"(r) : "f"(f));
    return r;
}
__device__ __forceinline__ void mma_tf32(float (&d)[4], const unsigned (&a)[4],
                                         const unsigned (&b)[2]) {
    asm volatile(
        "mma.sync.aligned.m16n8k8.row.col.f32.tf32.tf32.f32 "
        "{%0,%1,%2,%3}, {%4,%5,%6,%7}, {%8,%9}, {%0,%1,%2,%3};"
        : "+f"(d[0]), "+f"(d[1]), "+f"(d[2]), "+f"(d[3])
        : "r"(a[0]), "r"(a[1]), "r"(a[2]), "r"(a[3]), "r"(b[0]), "r"(b[1]));
}
__device__ __forceinline__ void cp16(void* dst_smem, const void* src) {
    unsigned int d = (unsigned int)__cvta_generic_to_shared(dst_smem);
    asm volatile("cp.async.cg.shared.global [%0], [%1], 16;"
                 :: "r"(d), "l"(src) : "memory");
}
__device__ __forceinline__ void cp_commit() {
    asm volatile("cp.async.commit_group;" ::: "memory");
}
template <int N>
__device__ __forceinline__ void cp_wait() {
    asm volatile("cp.async.wait_group %0;" :: "n"(N) : "memory");
}

__global__ __launch_bounds__(BLK, 5)
void qmha_kernel(const float* __restrict__ x,
                 const float* __restrict__ theta,
                 const float* __restrict__ w,      // [16][16] row-major w[o][e]
                 float* __restrict__ out,
                 int ntok)
{
    __shared__ float sW[256];
    // padded stage rows: 5 float4 (80B) per token; pad slot [4] never written
    __shared__ __align__(16) float4 sx[S][GT][5];   // 40KB

    const int tid  = threadIdx.x;
    const int lane = tid & 31;
    const int wid  = tid >> 5;
    const int tr   = lane >> 2;   // fragment row (token within tile half)
    const int tc   = lane & 3;    // fragment col

    sW[tid * 2 + 0] = w[tid * 2 + 0];
    sW[tid * 2 + 1] = w[tid * 2 + 1];
    __syncthreads();

    // B fragments: B[k][n] = W[nh*8+n][ks*8+k], col-major fragment:
    //   b0 = B[tc][tr] = W[nh*8+tr][ks*8+tc], b1 = B[tc+4][tr]
    unsigned bh[2][2][2], bl[2][2][2];   // [kstep][nhalf][reg]
#pragma unroll
    for (int ks = 0; ks < 2; ks++)
#pragma unroll
        for (int nh = 0; nh < 2; nh++) {
            const float w0 = sW[(nh * 8 + tr) * 16 + ks * 8 + tc];
            const float w1 = sW[(nh * 8 + tr) * 16 + ks * 8 + tc + 4];
            bh[ks][nh][0] = f2tf(w0);
            bl[ks][nh][0] = f2tf(w0 - __uint_as_float(bh[ks][nh][0]));
            bh[ks][nh][1] = f2tf(w1);
            bl[ks][nh][1] = f2tf(w1 - __uint_as_float(bh[ks][nh][1]));
        }

    // theta for this lane's fragment columns: e = tc + 4*m
    float thv[4];
#pragma unroll
    for (int m = 0; m < 4; m++) thv[m] = theta[tc + 4 * m];

    const int nblk = gridDim.x;
    const int bid  = blockIdx.x;
    const int ngrp = ntok / GT;

    // ---- prefill S-1 stages (4 cp.async 16B per thread per stage) ----
    int gp = bid;
#pragma unroll
    for (int s = 0; s < S - 1; s++) {
        if (gp < ngrp) {
            const float4* src = (const float4*)x + (size_t)gp * (GT * 4);
#pragma unroll
            for (int c = 0; c < 4; c++) {
                const int idx = tid + c * BLK;     // 0..511 data chunks
                cp16(&sx[s][idx >> 2][idx & 3], src + idx);
            }
        }
        cp_commit();
        gp += nblk;
    }

    int it = 0;
    for (int g = bid; g < ngrp; g += nblk, it++) {
        cp_wait<S - 2>();
        __syncthreads();

        // refill freed slot
        {
            const int ws = (it + S - 1) % S;
            if (gp < ngrp) {
                const float4* src = (const float4*)x + (size_t)gp * (GT * 4);
#pragma unroll
                for (int c = 0; c < 4; c++) {
                    const int idx = tid + c * BLK;
                    cp16(&sx[ws][idx >> 2][idx & 3], src + idx);
                }
            }
            cp_commit();
            gp += nblk;
        }

        // consume: 8 tiles of 16 tokens; warp handles tiles wid, wid+4
        const int cs = it % S;
        const float* sf = (const float*)sx[cs];
        float* outg = out + (size_t)g * GT * 16;

#pragma unroll
        for (int k2 = 0; k2 < 2; k2++) {
            const int tile = wid + 4 * k2;
            const float* r0 = sf + (tile * 16 + tr) * ROWF;
            const float* r8 = r0 + 8 * ROWF;

            float d0[4] = {0.f, 0.f, 0.f, 0.f};
            float d1[4] = {0.f, 0.f, 0.f, 0.f};
#pragma unroll
            for (int ks = 0; ks < 2; ks++) {
                const int c0 = tc + 8 * ks;
                const float z0 = __cosf(r0[c0]     + thv[2 * ks]);
                const float z1 = __cosf(r8[c0]     + thv[2 * ks]);
                const float z2 = __cosf(r0[c0 + 4] + thv[2 * ks + 1]);
                const float z3 = __cosf(r8[c0 + 4] + thv[2 * ks + 1]);

                unsigned ah[4], al[4];
                ah[0] = f2tf(z0); al[0] = f2tf(z0 - __uint_as_float(ah[0]));
                ah[1] = f2tf(z1); al[1] = f2tf(z1 - __uint_as_float(ah[1]));
                ah[2] = f2tf(z2); al[2] = f2tf(z2 - __uint_as_float(ah[2]));
                ah[3] = f2tf(z3); al[3] = f2tf(z3 - __uint_as_float(ah[3]));

                // 3xTF32: hi*hi + lo*hi + hi*lo (lo*lo ~2^-22, dropped)
                mma_tf32(d0, ah, bh[ks][0]); mma_tf32(d1, ah, bh[ks][1]);
                mma_tf32(d0, al, bh[ks][0]); mma_tf32(d1, al, bh[ks][1]);
                mma_tf32(d0, ah, bl[ks][0]); mma_tf32(d1, ah, bl[ks][1]);
            }

            // D fragment: c0/c1 = y[t0+tr][nh*8 + 2tc (+1)], c2/c3 = rows +8
            float2* o2 = (float2*)(outg + tile * 16 * 16);
            __stcs(&o2[tr * 8 + tc],           make_float2(d0[0], d0[1]));
            __stcs(&o2[tr * 8 + 4 + tc],       make_float2(d1[0], d1[1]));
            __stcs(&o2[(tr + 8) * 8 + tc],     make_float2(d0[2], d0[3]));
            __stcs(&o2[(tr + 8) * 8 + 4 + tc], make_float2(d1[2], d1[3]));
        }
    }

    // ---- generic scalar tail (ntok % GT) — unused at this shape ----
    const int tstart = ngrp * GT;
    if (bid == 0 && tstart < ntok) {
        for (int tok = tstart + tid; tok < ntok; tok += BLK) {
            float z[16];
#pragma unroll
            for (int e = 0; e < 16; e++)
                z[e] = __cosf(x[(size_t)tok * 16 + e] + theta[e]);
#pragma unroll
            for (int o = 0; o < 16; o++) {
                float a = 0.f;
#pragma unroll
                for (int e = 0; e < 16; e++) a += z[e] * sW[o * 16 + e];
                out[(size_t)tok * 16 + o] = a;
            }
        }
    }
}

extern "C" void kernel_launch(void* const* d_in, const int* in_sizes, int n_in,
                              void* d_out, int out_size) {
    const float* x     = (const float*)d_in[0];   // [B, S, 16] f32
    const float* theta = (const float*)d_in[1];   // [16] f32
    const float* w     = (const float*)d_in[2];   // [16, 16] f32
    float* out         = (float*)d_out;           // [B, S, 16] f32

    const int ntok = in_sizes[0] / 16;
    const int ngrp = ntok / GT;

    int blocks = 148 * 5;
    if (ngrp > 0 && blocks > ngrp) blocks = ngrp;
    if (blocks < 1) blocks = 1;

    qmha_kernel<<<blocks, BLK>>>(x, theta, w, out, ntok);
}

// round 17
// speedup vs baseline: 1.1515x; 1.1515x over previous
#include <cuda_runtime.h>

// y[tok][o] = sum_e cos(x[tok][e] + theta[e]) * W[o][e],  E = 16, ntok = 1,048,576
//
// cp.async 3-stage smem ring, 128 tokens/stage, rows padded to 24 floats
// (conflict-free LDS.64 for MMA A-fragments). Per warp: 16-token tiles on
// tensor cores via mma.m16n8k16.bf16 with 3-term bf16 split
// (zh*wh + zl*wh + zh*wl), fp32 accum -> rel err ~1e-5.

#define BLK  128
#define S    3        // pipeline stages
#define GT   128      // tokens per stage
#define ROWF 24       // floats per padded token row (16 data + 8 pad)

__device__ __forceinline__ unsigned cvtbf2(float hi, float lo) {
    unsigned r;
    asm("cvt.rn.bf16x2.f32 %0, %1, %2;" : "=r"(r) : "f"(hi), "f"(lo));
    return r;
}
__device__ __forceinline__ float bflo(unsigned u) { return __uint_as_float(u << 16); }
__device__ __forceinline__ float bfhi(unsigned u) { return __uint_as_float(u & 0xFFFF0000u); }

__device__ __forceinline__ void mma_bf16(float (&d)[4], const unsigned (&a)[4],
                                         const unsigned (&b)[2]) {
    asm volatile(
        "mma.sync.aligned.m16n8k16.row.col.f32.bf16.bf16.f32 "
        "{%0,%1,%2,%3}, {%4,%5,%6,%7}, {%8,%9}, {%0,%1,%2,%3};"
        : "+f"(d[0]), "+f"(d[1]), "+f"(d[2]), "+f"(d[3])
        : "r"(a[0]), "r"(a[1]), "r"(a[2]), "r"(a[3]), "r"(b[0]), "r"(b[1]));
}
__device__ __forceinline__ void cp16(void* dst_smem, const void* src) {
    unsigned int d = (unsigned int)__cvta_generic_to_shared(dst_smem);
    asm volatile("cp.async.cg.shared.global [%0], [%1], 16;"
                 :: "r"(d), "l"(src) : "memory");
}
__device__ __forceinline__ void cp_commit() {
    asm volatile("cp.async.commit_group;" ::: "memory");
}
template <int N>
__device__ __forceinline__ void cp_wait() {
    asm volatile("cp.async.wait_group %0;" :: "n"(N) : "memory");
}

__global__ __launch_bounds__(BLK, 5)
void qmha_kernel(const float* __restrict__ x,
                 const float* __restrict__ theta,
                 const float* __restrict__ w,      // [16][16] row-major w[o][e]
                 float* __restrict__ out,
                 int ntok)
{
    __shared__ float sW[256];
    __shared__ __align__(16) float4 sx[S][GT][ROWF / 4];   // 36KB ring

    const int tid  = threadIdx.x;
    const int lane = tid & 31;
    const int wid  = tid >> 5;
    const int tr   = lane >> 2;   // fragment row group
    const int tc   = lane & 3;    // fragment col group

    sW[tid * 2 + 0] = w[tid * 2 + 0];
    sW[tid * 2 + 1] = w[tid * 2 + 1];
    __syncthreads();

    // B fragments (col-major k16n8): b0 = {W[n0+tr][2tc+1] | W[n0+tr][2tc]},
    // b1 = same with k+8. hi = bf16(w), lo = bf16(w - f32(hi)).
    unsigned bh[2][2], bl[2][2];   // [nhalf][reg]
#pragma unroll
    for (int nh = 0; nh < 2; nh++) {
        const float* wr = sW + (nh * 8 + tr) * 16;
        const float w0 = wr[2 * tc], w1 = wr[2 * tc + 1];
        const float w2 = wr[8 + 2 * tc], w3 = wr[9 + 2 * tc];
        bh[nh][0] = cvtbf2(w1, w0);
        bh[nh][1] = cvtbf2(w3, w2);
        bl[nh][0] = cvtbf2(w1 - bfhi(bh[nh][0]), w0 - bflo(bh[nh][0]));
        bl[nh][1] = cvtbf2(w3 - bfhi(bh[nh][1]), w2 - bflo(bh[nh][1]));
    }

    // theta for this lane's k columns
    const float th00 = theta[2 * tc],     th01 = theta[2 * tc + 1];
    const float th10 = theta[8 + 2 * tc], th11 = theta[9 + 2 * tc];

    const int nblk = gridDim.x;
    const int bid  = blockIdx.x;
    const int ngrp = ntok / GT;

    // ---- prefill S-1 stages (4 cp.async 16B per thread per stage) ----
    int gp = bid;
#pragma unroll
    for (int s = 0; s < S - 1; s++) {
        if (gp < ngrp) {
            const float4* src = (const float4*)x + (size_t)gp * (GT * 4);
#pragma unroll
            for (int c = 0; c < 4; c++) {
                const int idx = tid + c * BLK;     // 0..511 data chunks
                cp16(&sx[s][idx >> 2][idx & 3], src + idx);
            }
        }
        cp_commit();
        gp += nblk;
    }

    int it = 0;
    for (int g = bid; g < ngrp; g += nblk, it++) {
        cp_wait<S - 2>();
        __syncthreads();

        // refill freed slot
        {
            const int ws = (it + S - 1) % S;
            if (gp < ngrp) {
                const float4* src = (const float4*)x + (size_t)gp * (GT * 4);
#pragma unroll
                for (int c = 0; c < 4; c++) {
                    const int idx = tid + c * BLK;
                    cp16(&sx[ws][idx >> 2][idx & 3], src + idx);
                }
            }
            cp_commit();
            gp += nblk;
        }

        // consume: 8 tiles of 16 tokens; warp handles tiles wid, wid+4
        const int cs = it % S;
        const float* sf = (const float*)sx[cs];
        float* outg = out + (size_t)g * GT * 16;

#pragma unroll
        for (int k2 = 0; k2 < 2; k2++) {
            const int tile = wid + 4 * k2;
            const float* r0 = sf + (tile * 16 + tr) * ROWF;
            const float* r8 = r0 + 8 * ROWF;

            // A fragment sources: rows tr, tr+8; k pairs {2tc,2tc+1},{8+2tc,9+2tc}
            const float2 v00 = *(const float2*)(r0 + 2 * tc);
            const float2 v10 = *(const float2*)(r8 + 2 * tc);
            const float2 v01 = *(const float2*)(r0 + 8 + 2 * tc);
            const float2 v11 = *(const float2*)(r8 + 8 + 2 * tc);

            const float z0x = __cosf(v00.x + th00), z0y = __cosf(v00.y + th01);
            const float z1x = __cosf(v10.x + th00), z1y = __cosf(v10.y + th01);
            const float z2x = __cosf(v01.x + th10), z2y = __cosf(v01.y + th11);
            const float z3x = __cosf(v11.x + th10), z3y = __cosf(v11.y + th11);

            unsigned ah[4], al[4];
            ah[0] = cvtbf2(z0y, z0x);
            ah[1] = cvtbf2(z1y, z1x);
            ah[2] = cvtbf2(z2y, z2x);
            ah[3] = cvtbf2(z3y, z3x);
            al[0] = cvtbf2(z0y - bfhi(ah[0]), z0x - bflo(ah[0]));
            al[1] = cvtbf2(z1y - bfhi(ah[1]), z1x - bflo(ah[1]));
            al[2] = cvtbf2(z2y - bfhi(ah[2]), z2x - bflo(ah[2]));
            al[3] = cvtbf2(z3y - bfhi(ah[3]), z3x - bflo(ah[3]));

            float d0[4] = {0.f, 0.f, 0.f, 0.f};
            float d1[4] = {0.f, 0.f, 0.f, 0.f};
            // 3-term bf16: hi*wh + lo*wh + hi*wl  (lo*wl ~ 2^-18, dropped)
            mma_bf16(d0, ah, bh[0]);  mma_bf16(d1, ah, bh[1]);
            mma_bf16(d0, al, bh[0]);  mma_bf16(d1, al, bh[1]);
            mma_bf16(d0, ah, bl[0]);  mma_bf16(d1, ah, bl[1]);

            // D fragment (same layout as m16n8k8): c0/c1 = row tr cols {2tc,2tc+1},
            // c2/c3 = row tr+8; d1 = n+8.
            float2* o2 = (float2*)(outg + tile * 16 * 16);
            __stcs(&o2[tr * 8 + tc],           make_float2(d0[0], d0[1]));
            __stcs(&o2[tr * 8 + 4 + tc],       make_float2(d1[0], d1[1]));
            __stcs(&o2[(tr + 8) * 8 + tc],     make_float2(d0[2], d0[3]));
            __stcs(&o2[(tr + 8) * 8 + 4 + tc], make_float2(d1[2], d1[3]));
        }
    }

    // ---- generic scalar tail (ntok % GT) — unused at this shape ----
    const int tstart = ngrp * GT;
    if (bid == 0 && tstart < ntok) {
        for (int tok = tstart + tid; tok < ntok; tok += BLK) {
            float z[16];
#pragma unroll
            for (int e = 0; e < 16; e++)
                z[e] = __cosf(x[(size_t)tok * 16 + e] + theta[e]);
#pragma unroll
            for (int o = 0; o < 16; o++) {
                float a = 0.f;
#pragma unroll
                for (int e = 0; e < 16; e++) a += z[e] * sW[o * 16 + e];
                out[(size_t)tok * 16 + o] = a;
            }
        }
    }
}

extern "C" void kernel_launch(void* const* d_in, const int* in_sizes, int n_in,
                              void* d_out, int out_size) {
    const float* x     = (const float*)d_in[0];   // [B, S, 16] f32
    const float* theta = (const float*)d_in[1];   // [16] f32
    const float* w     = (const float*)d_in[2];   // [16, 16] f32
    float* out         = (float*)d_out;           // [B, S, 16] f32

    const int ntok = in_sizes[0] / 16;
    const int ngrp = ntok / GT;

    int blocks = 148 * 5;
    if (ngrp > 0 && blocks > ngrp) blocks = ngrp;
    if (blocks < 1) blocks = 1;

    qmha_kernel<<<blocks, BLK>>>(x, theta, w, out, ntok);
}